// round 7
// baseline (speedup 1.0000x reference)
#include <cuda_runtime.h>
#include <cuda_fp16.h>
#include <math.h>
#include <stdint.h>

// ---------------------------------------------------------------------------
// Problem constants
// ---------------------------------------------------------------------------
#define B_SZ    2
#define S_LEN   2048
#define D_IN    2048
#define D_OUT   2048
#define NHEAD   16
#define DH      128
#define D3      6144
#define M_TOK   (B_SZ * S_LEN)
#define QSCALE  0.08838834764831843f   // 1/sqrt(128)

// Scratch (fp16 operands; weights split hi/lo, activations single)
__device__ __half g_x16[(size_t)M_TOK * D_IN];
__device__ __half g_wqh[(size_t)D3 * D_IN];
__device__ __half g_wql[(size_t)D3 * D_IN];
__device__ __half g_wph[(size_t)D_OUT * D_OUT];
__device__ __half g_wpl[(size_t)D_OUT * D_OUT];
__device__ __half g_qkvh[(size_t)M_TOK * D3];
__device__ __half g_qkvl[(size_t)M_TOK * D3];   // lo only written for Q cols
__device__ __half g_a16[(size_t)M_TOK * D_OUT];

// ---------------------------------------------------------------------------
// Helpers
// ---------------------------------------------------------------------------
__device__ __forceinline__ uint32_t smem_u32(const void* p) {
    uint32_t a;
    asm("{ .reg .u64 t; cvta.to.shared.u64 t, %1; cvt.u32.u64 %0, t; }" : "=r"(a) : "l"(p));
    return a;
}
__device__ __forceinline__ uint32_t packh2(float x, float y) {
    __half2 h = __floats2half2_rn(x, y);
    return *reinterpret_cast<uint32_t*>(&h);
}
__device__ __forceinline__ void split2h(float x, float y, uint32_t& hi, uint32_t& lo) {
    __half hx = __float2half_rn(x), hy = __float2half_rn(y);
    float rx = x - __half2float(hx), ry = y - __half2float(hy);
    __half2 h2 = __halves2half2(hx, hy);
    __half2 l2 = __halves2half2(__float2half_rn(rx), __float2half_rn(ry));
    hi = *reinterpret_cast<uint32_t*>(&h2);
    lo = *reinterpret_cast<uint32_t*>(&l2);
}
__device__ __forceinline__ void ldsm4(uint32_t* r, uint32_t addr) {
    asm volatile("ldmatrix.sync.aligned.m8n8.x4.shared.b16 {%0,%1,%2,%3}, [%4];"
                 : "=r"(r[0]), "=r"(r[1]), "=r"(r[2]), "=r"(r[3]) : "r"(addr));
}
__device__ __forceinline__ void ldsm4t(uint32_t* r, uint32_t addr) {
    asm volatile("ldmatrix.sync.aligned.m8n8.x4.trans.shared.b16 {%0,%1,%2,%3}, [%4];"
                 : "=r"(r[0]), "=r"(r[1]), "=r"(r[2]), "=r"(r[3]) : "r"(addr));
}
__device__ __forceinline__ void mma_f16(float* c, const uint32_t* a, uint32_t b0, uint32_t b1) {
    asm volatile(
        "mma.sync.aligned.m16n8k16.row.col.f32.f16.f16.f32 "
        "{%0,%1,%2,%3}, {%4,%5,%6,%7}, {%8,%9}, {%0,%1,%2,%3};"
        : "+f"(c[0]), "+f"(c[1]), "+f"(c[2]), "+f"(c[3])
        : "r"(a[0]), "r"(a[1]), "r"(a[2]), "r"(a[3]), "r"(b0), "r"(b1));
}
__device__ __forceinline__ void cp16(uint32_t dst, const void* src) {
    asm volatile("cp.async.cg.shared.global [%0], [%1], 16;" :: "r"(dst), "l"(src));
}
#define CP_COMMIT() asm volatile("cp.async.commit_group;" ::: "memory")
#define CP_WAIT(n)  asm volatile("cp.async.wait_group %0;" :: "n"(n) : "memory")

// ---------------------------------------------------------------------------
// Conversion kernels
// ---------------------------------------------------------------------------
__global__ void tohalf_k(const float4* __restrict__ in, uint2* __restrict__ out, int n4)
{
    int i = blockIdx.x * blockDim.x + threadIdx.x;
    if (i >= n4) return;
    float4 v = in[i];
    out[i] = make_uint2(packh2(v.x, v.y), packh2(v.z, v.w));
}
__global__ void splith_k(const float4* __restrict__ in, uint2* __restrict__ hi,
                         uint2* __restrict__ lo, int n4)
{
    int i = blockIdx.x * blockDim.x + threadIdx.x;
    if (i >= n4) return;
    float4 v = in[i];
    uint32_t h0, l0, h1, l1;
    split2h(v.x, v.y, h0, l0);
    split2h(v.z, v.w, h1, l1);
    hi[i] = make_uint2(h0, h1);
    lo[i] = make_uint2(l0, l1);
}

// ---------------------------------------------------------------------------
// fp16 split tensor-core GEMM: C = A @ (Bh+Bl)^T.
// A single fp16, B split hi/lo. 128x128 tile, BK=32, cp.async double-buffered.
// Out: f32 (+bias) OR split fp16 (Q cols scaled by qscale, lo only for Q cols).
// ---------------------------------------------------------------------------
#define GBK      32
#define ROWB     80                    // 32 fp16 (64B) + 16B pad
#define TILE_BY  (128 * ROWB)          // 10240
#define STAGE_BY (3 * TILE_BY)         // 30720
#define GEMM_SMEM (2 * STAGE_BY)       // 61440

__global__ __launch_bounds__(256, 2)
void mma_gemm(const __half* __restrict__ A,
              const __half* __restrict__ Bh, const __half* __restrict__ Bl,
              const float* __restrict__ bias, float* __restrict__ C,
              __half* __restrict__ Ch, __half* __restrict__ Cl,
              int M, int N, int K, float qscale, int qcols)
{
    extern __shared__ char smem[];
    const uint32_t sb = smem_u32(smem);

    const int tid  = threadIdx.x;
    const int wid  = tid >> 5, lane = tid & 31;
    const int m0   = blockIdx.y << 7;
    const int n0   = blockIdx.x << 7;
    const int wm   = (wid & 3) * 32;
    const int wn   = (wid >> 2) * 64;

    const __half* baseA  = A  + (size_t)m0 * K;
    const __half* baseBh = Bh + (size_t)n0 * K;
    const __half* baseBl = Bl + (size_t)n0 * K;

    const uint32_t aoff = (uint32_t)(wm + (lane & 15)) * ROWB + (lane >> 4) * 16;
    const uint32_t boff = (uint32_t)(wn + (lane & 15)) * ROWB + (lane >> 4) * 16;

    float acc[2][8][4];
#pragma unroll
    for (int mt = 0; mt < 2; ++mt)
#pragma unroll
        for (int nb = 0; nb < 8; ++nb)
#pragma unroll
            for (int e = 0; e < 4; ++e) acc[mt][nb][e] = 0.f;

    auto load_chunk = [&](int stage, int k0) {
        const uint32_t sbase = sb + stage * STAGE_BY;
        const int seg = tid & 3;
        const int r0 = tid >> 2;
#pragma unroll
        for (int i = 0; i < 6; ++i) {
            const int tile = i >> 1;
            const int row = (i & 1) * 64 + r0;
            const __half* bp = (tile == 0) ? baseA : (tile == 1) ? baseBh : baseBl;
            cp16(sbase + tile * TILE_BY + row * ROWB + seg * 16,
                 bp + (size_t)row * K + k0 + seg * 8);
        }
    };

    const int nchunk = K / GBK;
    load_chunk(0, 0);
    CP_COMMIT();

    for (int i = 0; i < nchunk; ++i) {
        if (i + 1 < nchunk) {
            load_chunk((i + 1) & 1, (i + 1) * GBK);
            CP_COMMIT();
            CP_WAIT(1);
        } else {
            CP_WAIT(0);
        }
        __syncthreads();

        const uint32_t st = sb + (i & 1) * STAGE_BY;
        const uint32_t sA = st, sBh2 = st + TILE_BY, sBl2 = st + 2 * TILE_BY;
#pragma unroll
        for (int ks = 0; ks < 2; ++ks) {
            uint32_t a[2][4];
#pragma unroll
            for (int mt = 0; mt < 2; ++mt)
                ldsm4(a[mt], sA + aoff + mt * 16 * ROWB + ks * 32);
#pragma unroll
            for (int pg = 0; pg < 4; ++pg) {
                uint32_t bh[4], bl[4];
                ldsm4(bh, sBh2 + boff + pg * 16 * ROWB + ks * 32);
                ldsm4(bl, sBl2 + boff + pg * 16 * ROWB + ks * 32);
#pragma unroll
                for (int mt = 0; mt < 2; ++mt) {
                    mma_f16(acc[mt][pg * 2],     a[mt], bh[0], bh[2]);
                    mma_f16(acc[mt][pg * 2],     a[mt], bl[0], bl[2]);
                    mma_f16(acc[mt][pg * 2 + 1], a[mt], bh[1], bh[3]);
                    mma_f16(acc[mt][pg * 2 + 1], a[mt], bl[1], bl[3]);
                }
            }
        }
        __syncthreads();
    }

    const int crow = lane >> 2;
    const int ccol = (lane & 3) * 2;
    if (C) {
#pragma unroll
        for (int mt = 0; mt < 2; ++mt)
#pragma unroll
            for (int nb = 0; nb < 8; ++nb) {
                const int row = m0 + wm + mt * 16 + crow;
                const int col = n0 + wn + nb * 8 + ccol;
                float2 v0 = make_float2(acc[mt][nb][0], acc[mt][nb][1]);
                float2 v1 = make_float2(acc[mt][nb][2], acc[mt][nb][3]);
                if (bias) {
                    float2 bv = *(const float2*)(bias + col);
                    v0.x += bv.x; v0.y += bv.y;
                    v1.x += bv.x; v1.y += bv.y;
                }
                *(float2*)(C + (size_t)row * N + col)       = v0;
                *(float2*)(C + (size_t)(row + 8) * N + col) = v1;
            }
    } else {
#pragma unroll
        for (int mt = 0; mt < 2; ++mt)
#pragma unroll
            for (int nb = 0; nb < 8; ++nb) {
                const int row = m0 + wm + mt * 16 + crow;
                const int col = n0 + wn + nb * 8 + ccol;
                const bool isq = (col < qcols);
                const float s = isq ? qscale : 1.f;
                uint32_t h0, l0, h1, l1;
                split2h(acc[mt][nb][0] * s, acc[mt][nb][1] * s, h0, l0);
                split2h(acc[mt][nb][2] * s, acc[mt][nb][3] * s, h1, l1);
                *(uint32_t*)(Ch + (size_t)row * N + col)       = h0;
                *(uint32_t*)(Ch + (size_t)(row + 8) * N + col) = h1;
                if (isq) {
                    *(uint32_t*)(Cl + (size_t)row * N + col)       = l0;
                    *(uint32_t*)(Cl + (size_t)(row + 8) * N + col) = l1;
                }
            }
    }
}

// ---------------------------------------------------------------------------
// Tensor-core causal flash attention, fp16.
// scores: (Qh+Ql) · K   (Q pre-scaled, split; K single)   — 2 MMAs/frag
// PV:     P · V         (P, V single fp16)                — 1 MMA/frag
// BQ=128 (8 warps x 16 rows), BK=64, K/V double-buffered cp.async.
// ---------------------------------------------------------------------------
#define ASTR    272                    // 128 fp16 (256B) + 16B pad
#define QTILE_B (128 * ASTR)           // 34816
#define KVTILE  (64 * ASTR)            // 17408
#define KVSTAGE (2 * KVTILE)           // 34816 (K + V)
#define OFF_KV  (2 * QTILE_B)          // 69632
#define ATTN_SMEM_B (OFF_KV + 2 * KVSTAGE)   // 139264

__global__ __launch_bounds__(256, 1)
void attn_mma(const __half* __restrict__ qh, const __half* __restrict__ ql,
              __half* __restrict__ oh)
{
    extern __shared__ char smx[];
    const uint32_t sb = smem_u32(smx);

    const int t = threadIdx.x, w = t >> 5, lane = t & 31;
    const int qtile = (int)gridDim.x - 1 - (int)blockIdx.x;
    const int bh = blockIdx.y;
    const int b = bh >> 4, h = bh & 15;
    const int qt0 = qtile * 128;
    const int wm = w * 16;

    // ---- issue Q (hi+lo, pre-scaled) ----
    {
        const int seg = t & 15, r0 = t >> 4;
#pragma unroll
        for (int i = 0; i < 16; ++i) {
            const int tile = i >> 3;               // 0=hi, 1=lo
            const int row = (i & 7) * 16 + r0;
            const __half* src = (tile ? ql : qh)
                + (size_t)(b * S_LEN + qt0 + row) * D3 + h * DH + seg * 8;
            cp16(sb + tile * QTILE_B + row * ASTR + seg * 16, src);
        }
    }

    auto kv_load = [&](int kt, int s) {
        const int seg = t & 15, r0 = t >> 4;
        const uint32_t sbase = sb + OFF_KV + s * KVSTAGE;
#pragma unroll
        for (int i = 0; i < 8; ++i) {
            const int tile = i >> 2;               // 0=K, 1=V
            const int row = (i & 3) * 16 + r0;
            const __half* src = qh
                + (size_t)(b * S_LEN + kt * 64 + row) * D3
                + D_OUT + tile * D_OUT + h * DH + seg * 8;
            cp16(sbase + tile * KVTILE + row * ASTR + seg * 16, src);
        }
    };

    kv_load(0, 0);
    CP_COMMIT();

    const uint32_t qbh = sb + (uint32_t)(wm + (lane & 15)) * ASTR + (lane >> 4) * 16;
    const uint32_t qbl = qbh + QTILE_B;
    const uint32_t klo = (uint32_t)(lane & 15) * ASTR + (lane >> 4) * 16;
    const uint32_t vlo = (uint32_t)(((lane >> 4) << 3) + (lane & 7)) * ASTR
                         + ((lane >> 3) & 1) * 16;

    float o[16][4];
#pragma unroll
    for (int nb = 0; nb < 16; ++nb)
#pragma unroll
        for (int e = 0; e < 4; ++e) o[nb][e] = 0.f;
    float m_a = -1e30f, m_b = -1e30f, l_a = 0.f, l_b = 0.f;

    const int row_a = qt0 + wm + (lane >> 2);
    const int row_b = row_a + 8;

    const int nkt = (qt0 + 128) / 64;
    for (int kt = 0; kt < nkt; ++kt) {
        if (kt + 1 < nkt) {
            kv_load(kt + 1, (kt + 1) & 1);
            CP_COMMIT();
            CP_WAIT(1);
        } else {
            CP_WAIT(0);
        }
        __syncthreads();

        if (kt * 64 <= qt0 + wm + 15) {
            const uint32_t stb = sb + OFF_KV + (kt & 1) * KVSTAGE;
            const uint32_t kb = stb + klo;
            const uint32_t vb = stb + KVTILE + vlo;

            // ---- scores ----
            float sacc[8][4];
#pragma unroll
            for (int nb = 0; nb < 8; ++nb)
#pragma unroll
                for (int e = 0; e < 4; ++e) sacc[nb][e] = 0.f;

#pragma unroll
            for (int ks = 0; ks < 8; ++ks) {
                uint32_t ah[4], al[4];
                ldsm4(ah, qbh + ks * 32);
                ldsm4(al, qbl + ks * 32);
#pragma unroll
                for (int pg = 0; pg < 4; ++pg) {
                    uint32_t bk[4];
                    ldsm4(bk, kb + pg * 16 * ASTR + ks * 32);
                    mma_f16(sacc[pg * 2],     ah, bk[0], bk[2]);
                    mma_f16(sacc[pg * 2],     al, bk[0], bk[2]);
                    mma_f16(sacc[pg * 2 + 1], ah, bk[1], bk[3]);
                    mma_f16(sacc[pg * 2 + 1], al, bk[1], bk[3]);
                }
            }

            // ---- causal mask ----
            if (kt * 64 + 63 > qt0 + wm) {
#pragma unroll
                for (int nb = 0; nb < 8; ++nb) {
                    const int col = kt * 64 + nb * 8 + (lane & 3) * 2;
                    if (col > row_a)     sacc[nb][0] = -1e30f;
                    if (col + 1 > row_a) sacc[nb][1] = -1e30f;
                    if (col > row_b)     sacc[nb][2] = -1e30f;
                    if (col + 1 > row_b) sacc[nb][3] = -1e30f;
                }
            }

            // ---- online softmax ----
            float mx_a = -1e30f, mx_b = -1e30f;
#pragma unroll
            for (int nb = 0; nb < 8; ++nb) {
                mx_a = fmaxf(mx_a, fmaxf(sacc[nb][0], sacc[nb][1]));
                mx_b = fmaxf(mx_b, fmaxf(sacc[nb][2], sacc[nb][3]));
            }
            mx_a = fmaxf(mx_a, __shfl_xor_sync(0xffffffffu, mx_a, 1));
            mx_a = fmaxf(mx_a, __shfl_xor_sync(0xffffffffu, mx_a, 2));
            mx_b = fmaxf(mx_b, __shfl_xor_sync(0xffffffffu, mx_b, 1));
            mx_b = fmaxf(mx_b, __shfl_xor_sync(0xffffffffu, mx_b, 2));

            const float mn_a = fmaxf(m_a, mx_a);
            const float mn_b = fmaxf(m_b, mx_b);
            const float al_a = __expf(m_a - mn_a);
            const float al_b = __expf(m_b - mn_b);
            m_a = mn_a; m_b = mn_b;

            float sum_a = 0.f, sum_b = 0.f;
#pragma unroll
            for (int nb = 0; nb < 8; ++nb) {
                sacc[nb][0] = __expf(sacc[nb][0] - mn_a);
                sacc[nb][1] = __expf(sacc[nb][1] - mn_a);
                sacc[nb][2] = __expf(sacc[nb][2] - mn_b);
                sacc[nb][3] = __expf(sacc[nb][3] - mn_b);
                sum_a += sacc[nb][0] + sacc[nb][1];
                sum_b += sacc[nb][2] + sacc[nb][3];
            }
            sum_a += __shfl_xor_sync(0xffffffffu, sum_a, 1);
            sum_a += __shfl_xor_sync(0xffffffffu, sum_a, 2);
            sum_b += __shfl_xor_sync(0xffffffffu, sum_b, 1);
            sum_b += __shfl_xor_sync(0xffffffffu, sum_b, 2);
            l_a = l_a * al_a + sum_a;
            l_b = l_b * al_b + sum_b;

#pragma unroll
            for (int nb = 0; nb < 16; ++nb) {
                o[nb][0] *= al_a; o[nb][1] *= al_a;
                o[nb][2] *= al_b; o[nb][3] *= al_b;
            }

            // ---- PV: P single fp16, V single fp16 ----
#pragma unroll
            for (int kc = 0; kc < 4; ++kc) {
                uint32_t p[4];
                p[0] = packh2(sacc[2 * kc][0],     sacc[2 * kc][1]);
                p[1] = packh2(sacc[2 * kc][2],     sacc[2 * kc][3]);
                p[2] = packh2(sacc[2 * kc + 1][0], sacc[2 * kc + 1][1]);
                p[3] = packh2(sacc[2 * kc + 1][2], sacc[2 * kc + 1][3]);
#pragma unroll
                for (int pg = 0; pg < 8; ++pg) {
                    uint32_t vv[4];
                    ldsm4t(vv, vb + kc * 16 * ASTR + pg * 32);
                    mma_f16(o[pg * 2],     p, vv[0], vv[2]);
                    mma_f16(o[pg * 2 + 1], p, vv[1], vv[3]);
                }
            }
        }
        __syncthreads();
    }

    // ---- epilogue: single fp16 output ----
    const float inv_a = 1.f / l_a;
    const float inv_b = 1.f / l_b;
    const size_t oa = (size_t)(b * S_LEN + row_a) * D_OUT + h * DH;
    const size_t ob = (size_t)(b * S_LEN + row_b) * D_OUT + h * DH;
#pragma unroll
    for (int nb = 0; nb < 16; ++nb) {
        const int col = nb * 8 + (lane & 3) * 2;
        *(uint32_t*)(oh + oa + col) = packh2(o[nb][0] * inv_a, o[nb][1] * inv_a);
        *(uint32_t*)(oh + ob + col) = packh2(o[nb][2] * inv_b, o[nb][3] * inv_b);
    }
}

// ---------------------------------------------------------------------------
// Launch
// ---------------------------------------------------------------------------
extern "C" void kernel_launch(void* const* d_in, const int* in_sizes, int n_in,
                              void* d_out, int out_size)
{
    const float* x      = (const float*)d_in[0];
    const float* w_qkv  = (const float*)d_in[1];
    const float* w_proj = (const float*)d_in[2];
    const float* b_proj = (const float*)d_in[3];
    float* out = (float*)d_out;

    void *x16, *wqh, *wql, *wph, *wpl, *qkvh, *qkvl, *a16;
    cudaGetSymbolAddress(&x16, g_x16);
    cudaGetSymbolAddress(&wqh, g_wqh); cudaGetSymbolAddress(&wql, g_wql);
    cudaGetSymbolAddress(&wph, g_wph); cudaGetSymbolAddress(&wpl, g_wpl);
    cudaGetSymbolAddress(&qkvh, g_qkvh); cudaGetSymbolAddress(&qkvl, g_qkvl);
    cudaGetSymbolAddress(&a16, g_a16);

    cudaFuncSetAttribute(mma_gemm, cudaFuncAttributeMaxDynamicSharedMemorySize, GEMM_SMEM);
    cudaFuncSetAttribute(attn_mma, cudaFuncAttributeMaxDynamicSharedMemorySize, ATTN_SMEM_B);

    // 0) conversions
    {
        int n4;
        n4 = M_TOK * D_IN / 4;
        tohalf_k<<<(n4 + 255) / 256, 256>>>((const float4*)x, (uint2*)x16, n4);
        n4 = D3 * D_IN / 4;
        splith_k<<<(n4 + 255) / 256, 256>>>((const float4*)w_qkv, (uint2*)wqh, (uint2*)wql, n4);
        n4 = D_OUT * D_OUT / 4;
        splith_k<<<(n4 + 255) / 256, 256>>>((const float4*)w_proj, (uint2*)wph, (uint2*)wpl, n4);
    }

    // 1) QKV projection -> split fp16 qkv (Q cols pre-scaled)
    mma_gemm<<<dim3(D3 / 128, M_TOK / 128), 256, GEMM_SMEM>>>(
        (const __half*)x16, (const __half*)wqh, (const __half*)wql,
        nullptr, nullptr, (__half*)qkvh, (__half*)qkvl,
        M_TOK, D3, D_IN, QSCALE, D_OUT);

    // 2) Fused causal attention -> single fp16
    attn_mma<<<dim3(S_LEN / 128, B_SZ * NHEAD), 256, ATTN_SMEM_B>>>(
        (const __half*)qkvh, (const __half*)qkvl, (__half*)a16);

    // 3) Output projection + bias -> f32 out
    mma_gemm<<<dim3(D_OUT / 128, M_TOK / 128), 256, GEMM_SMEM>>>(
        (const __half*)a16, (const __half*)wph, (const __half*)wpl,
        b_proj, out, nullptr, nullptr,
        M_TOK, D_OUT, D_OUT, 1.f, 0);
}

// round 8
// speedup vs baseline: 1.0001x; 1.0001x over previous
#include <cuda_runtime.h>
#include <cuda_fp16.h>
#include <math.h>
#include <stdint.h>

// ---------------------------------------------------------------------------
// Problem constants
// ---------------------------------------------------------------------------
#define B_SZ    2
#define S_LEN   2048
#define D_IN    2048
#define D_OUT   2048
#define NHEAD   16
#define DH      128
#define D3      6144
#define M_TOK   (B_SZ * S_LEN)
#define QSCALE  0.08838834764831843f   // 1/sqrt(128)

// Scratch (fp16 operands; weights split hi/lo, activations single)
__device__ __half g_x16[(size_t)M_TOK * D_IN];
__device__ __half g_wqh[(size_t)D3 * D_IN];
__device__ __half g_wql[(size_t)D3 * D_IN];
__device__ __half g_wph[(size_t)D_OUT * D_OUT];
__device__ __half g_wpl[(size_t)D_OUT * D_OUT];
__device__ __half g_qkvh[(size_t)M_TOK * D3];
__device__ __half g_qkvl[(size_t)M_TOK * D3];   // lo only written for Q cols
__device__ __half g_a16[(size_t)M_TOK * D_OUT];

// ---------------------------------------------------------------------------
// Helpers
// ---------------------------------------------------------------------------
__device__ __forceinline__ uint32_t smem_u32(const void* p) {
    uint32_t a;
    asm("{ .reg .u64 t; cvta.to.shared.u64 t, %1; cvt.u32.u64 %0, t; }" : "=r"(a) : "l"(p));
    return a;
}
__device__ __forceinline__ uint32_t packh2(float x, float y) {
    __half2 h = __floats2half2_rn(x, y);
    return *reinterpret_cast<uint32_t*>(&h);
}
__device__ __forceinline__ void split2h(float x, float y, uint32_t& hi, uint32_t& lo) {
    __half hx = __float2half_rn(x), hy = __float2half_rn(y);
    float rx = x - __half2float(hx), ry = y - __half2float(hy);
    __half2 h2 = __halves2half2(hx, hy);
    __half2 l2 = __halves2half2(__float2half_rn(rx), __float2half_rn(ry));
    hi = *reinterpret_cast<uint32_t*>(&h2);
    lo = *reinterpret_cast<uint32_t*>(&l2);
}
__device__ __forceinline__ void ldsm4(uint32_t* r, uint32_t addr) {
    asm volatile("ldmatrix.sync.aligned.m8n8.x4.shared.b16 {%0,%1,%2,%3}, [%4];"
                 : "=r"(r[0]), "=r"(r[1]), "=r"(r[2]), "=r"(r[3]) : "r"(addr));
}
__device__ __forceinline__ void ldsm4t(uint32_t* r, uint32_t addr) {
    asm volatile("ldmatrix.sync.aligned.m8n8.x4.trans.shared.b16 {%0,%1,%2,%3}, [%4];"
                 : "=r"(r[0]), "=r"(r[1]), "=r"(r[2]), "=r"(r[3]) : "r"(addr));
}
__device__ __forceinline__ void mma_f16(float* c, const uint32_t* a, uint32_t b0, uint32_t b1) {
    asm volatile(
        "mma.sync.aligned.m16n8k16.row.col.f32.f16.f16.f32 "
        "{%0,%1,%2,%3}, {%4,%5,%6,%7}, {%8,%9}, {%0,%1,%2,%3};"
        : "+f"(c[0]), "+f"(c[1]), "+f"(c[2]), "+f"(c[3])
        : "r"(a[0]), "r"(a[1]), "r"(a[2]), "r"(a[3]), "r"(b0), "r"(b1));
}
__device__ __forceinline__ void cp16(uint32_t dst, const void* src) {
    asm volatile("cp.async.cg.shared.global [%0], [%1], 16;" :: "r"(dst), "l"(src));
}
#define CP_COMMIT() asm volatile("cp.async.commit_group;" ::: "memory")
#define CP_WAIT(n)  asm volatile("cp.async.wait_group %0;" :: "n"(n) : "memory")

// ---------------------------------------------------------------------------
// Conversion kernels
// ---------------------------------------------------------------------------
__global__ void tohalf_k(const float4* __restrict__ in, uint2* __restrict__ out, int n4)
{
    int i = blockIdx.x * blockDim.x + threadIdx.x;
    if (i >= n4) return;
    float4 v = in[i];
    out[i] = make_uint2(packh2(v.x, v.y), packh2(v.z, v.w));
}
__global__ void splith_k(const float4* __restrict__ in, uint2* __restrict__ hi,
                         uint2* __restrict__ lo, int n4)
{
    int i = blockIdx.x * blockDim.x + threadIdx.x;
    if (i >= n4) return;
    float4 v = in[i];
    uint32_t h0, l0, h1, l1;
    split2h(v.x, v.y, h0, l0);
    split2h(v.z, v.w, h1, l1);
    hi[i] = make_uint2(h0, h1);
    lo[i] = make_uint2(l0, l1);
}

// ---------------------------------------------------------------------------
// fp16 split tensor-core GEMM: C = A @ (Bh+Bl)^T.
// A single fp16, B split hi/lo. 128x128 tile, BK=32, cp.async double-buffered.
// Out: f32 (+bias) OR split fp16 (Q cols scaled by qscale, lo only for Q cols).
// ---------------------------------------------------------------------------
#define GBK      32
#define ROWB     80                    // 32 fp16 (64B) + 16B pad
#define TILE_BY  (128 * ROWB)          // 10240
#define STAGE_BY (3 * TILE_BY)         // 30720
#define GEMM_SMEM (2 * STAGE_BY)       // 61440

__global__ __launch_bounds__(256, 2)
void mma_gemm(const __half* __restrict__ A,
              const __half* __restrict__ Bh, const __half* __restrict__ Bl,
              const float* __restrict__ bias, float* __restrict__ C,
              __half* __restrict__ Ch, __half* __restrict__ Cl,
              int M, int N, int K, float qscale, int qcols)
{
    extern __shared__ char smem[];
    const uint32_t sb = smem_u32(smem);

    const int tid  = threadIdx.x;
    const int wid  = tid >> 5, lane = tid & 31;
    const int m0   = blockIdx.y << 7;
    const int n0   = blockIdx.x << 7;
    const int wm   = (wid & 3) * 32;
    const int wn   = (wid >> 2) * 64;

    const __half* baseA  = A  + (size_t)m0 * K;
    const __half* baseBh = Bh + (size_t)n0 * K;
    const __half* baseBl = Bl + (size_t)n0 * K;

    const uint32_t aoff = (uint32_t)(wm + (lane & 15)) * ROWB + (lane >> 4) * 16;
    const uint32_t boff = (uint32_t)(wn + (lane & 15)) * ROWB + (lane >> 4) * 16;

    float acc[2][8][4];
#pragma unroll
    for (int mt = 0; mt < 2; ++mt)
#pragma unroll
        for (int nb = 0; nb < 8; ++nb)
#pragma unroll
            for (int e = 0; e < 4; ++e) acc[mt][nb][e] = 0.f;

    auto load_chunk = [&](int stage, int k0) {
        const uint32_t sbase = sb + stage * STAGE_BY;
        const int seg = tid & 3;
        const int r0 = tid >> 2;
#pragma unroll
        for (int i = 0; i < 6; ++i) {
            const int tile = i >> 1;
            const int row = (i & 1) * 64 + r0;
            const __half* bp = (tile == 0) ? baseA : (tile == 1) ? baseBh : baseBl;
            cp16(sbase + tile * TILE_BY + row * ROWB + seg * 16,
                 bp + (size_t)row * K + k0 + seg * 8);
        }
    };

    const int nchunk = K / GBK;
    load_chunk(0, 0);
    CP_COMMIT();

    for (int i = 0; i < nchunk; ++i) {
        if (i + 1 < nchunk) {
            load_chunk((i + 1) & 1, (i + 1) * GBK);
            CP_COMMIT();
            CP_WAIT(1);
        } else {
            CP_WAIT(0);
        }
        __syncthreads();

        const uint32_t st = sb + (i & 1) * STAGE_BY;
        const uint32_t sA = st, sBh2 = st + TILE_BY, sBl2 = st + 2 * TILE_BY;
#pragma unroll
        for (int ks = 0; ks < 2; ++ks) {
            uint32_t a[2][4];
#pragma unroll
            for (int mt = 0; mt < 2; ++mt)
                ldsm4(a[mt], sA + aoff + mt * 16 * ROWB + ks * 32);
#pragma unroll
            for (int pg = 0; pg < 4; ++pg) {
                uint32_t bh[4], bl[4];
                ldsm4(bh, sBh2 + boff + pg * 16 * ROWB + ks * 32);
                ldsm4(bl, sBl2 + boff + pg * 16 * ROWB + ks * 32);
#pragma unroll
                for (int mt = 0; mt < 2; ++mt) {
                    mma_f16(acc[mt][pg * 2],     a[mt], bh[0], bh[2]);
                    mma_f16(acc[mt][pg * 2],     a[mt], bl[0], bl[2]);
                    mma_f16(acc[mt][pg * 2 + 1], a[mt], bh[1], bh[3]);
                    mma_f16(acc[mt][pg * 2 + 1], a[mt], bl[1], bl[3]);
                }
            }
        }
        __syncthreads();
    }

    const int crow = lane >> 2;
    const int ccol = (lane & 3) * 2;
    if (C) {
#pragma unroll
        for (int mt = 0; mt < 2; ++mt)
#pragma unroll
            for (int nb = 0; nb < 8; ++nb) {
                const int row = m0 + wm + mt * 16 + crow;
                const int col = n0 + wn + nb * 8 + ccol;
                float2 v0 = make_float2(acc[mt][nb][0], acc[mt][nb][1]);
                float2 v1 = make_float2(acc[mt][nb][2], acc[mt][nb][3]);
                if (bias) {
                    float2 bv = *(const float2*)(bias + col);
                    v0.x += bv.x; v0.y += bv.y;
                    v1.x += bv.x; v1.y += bv.y;
                }
                *(float2*)(C + (size_t)row * N + col)       = v0;
                *(float2*)(C + (size_t)(row + 8) * N + col) = v1;
            }
    } else {
#pragma unroll
        for (int mt = 0; mt < 2; ++mt)
#pragma unroll
            for (int nb = 0; nb < 8; ++nb) {
                const int row = m0 + wm + mt * 16 + crow;
                const int col = n0 + wn + nb * 8 + ccol;
                const bool isq = (col < qcols);
                const float s = isq ? qscale : 1.f;
                uint32_t h0, l0, h1, l1;
                split2h(acc[mt][nb][0] * s, acc[mt][nb][1] * s, h0, l0);
                split2h(acc[mt][nb][2] * s, acc[mt][nb][3] * s, h1, l1);
                *(uint32_t*)(Ch + (size_t)row * N + col)       = h0;
                *(uint32_t*)(Ch + (size_t)(row + 8) * N + col) = h1;
                if (isq) {
                    *(uint32_t*)(Cl + (size_t)row * N + col)       = l0;
                    *(uint32_t*)(Cl + (size_t)(row + 8) * N + col) = l1;
                }
            }
    }
}

// ---------------------------------------------------------------------------
// Tensor-core causal flash attention, fp16.
// scores: (Qh+Ql) · K   (Q pre-scaled, split; K single)   — 2 MMAs/frag
// PV:     P · V         (P, V single fp16)                — 1 MMA/frag
// BQ=128 (8 warps x 16 rows), BK=64, K/V double-buffered cp.async.
// ---------------------------------------------------------------------------
#define ASTR    272                    // 128 fp16 (256B) + 16B pad
#define QTILE_B (128 * ASTR)           // 34816
#define KVTILE  (64 * ASTR)            // 17408
#define KVSTAGE (2 * KVTILE)           // 34816 (K + V)
#define OFF_KV  (2 * QTILE_B)          // 69632
#define ATTN_SMEM_B (OFF_KV + 2 * KVSTAGE)   // 139264

__global__ __launch_bounds__(256, 1)
void attn_mma(const __half* __restrict__ qh, const __half* __restrict__ ql,
              __half* __restrict__ oh)
{
    extern __shared__ char smx[];
    const uint32_t sb = smem_u32(smx);

    const int t = threadIdx.x, w = t >> 5, lane = t & 31;
    const int qtile = (int)gridDim.x - 1 - (int)blockIdx.x;
    const int bh = blockIdx.y;
    const int b = bh >> 4, h = bh & 15;
    const int qt0 = qtile * 128;
    const int wm = w * 16;

    // ---- issue Q (hi+lo, pre-scaled) ----
    {
        const int seg = t & 15, r0 = t >> 4;
#pragma unroll
        for (int i = 0; i < 16; ++i) {
            const int tile = i >> 3;               // 0=hi, 1=lo
            const int row = (i & 7) * 16 + r0;
            const __half* src = (tile ? ql : qh)
                + (size_t)(b * S_LEN + qt0 + row) * D3 + h * DH + seg * 8;
            cp16(sb + tile * QTILE_B + row * ASTR + seg * 16, src);
        }
    }

    auto kv_load = [&](int kt, int s) {
        const int seg = t & 15, r0 = t >> 4;
        const uint32_t sbase = sb + OFF_KV + s * KVSTAGE;
#pragma unroll
        for (int i = 0; i < 8; ++i) {
            const int tile = i >> 2;               // 0=K, 1=V
            const int row = (i & 3) * 16 + r0;
            const __half* src = qh
                + (size_t)(b * S_LEN + kt * 64 + row) * D3
                + D_OUT + tile * D_OUT + h * DH + seg * 8;
            cp16(sbase + tile * KVTILE + row * ASTR + seg * 16, src);
        }
    };

    kv_load(0, 0);
    CP_COMMIT();

    const uint32_t qbh = sb + (uint32_t)(wm + (lane & 15)) * ASTR + (lane >> 4) * 16;
    const uint32_t qbl = qbh + QTILE_B;
    const uint32_t klo = (uint32_t)(lane & 15) * ASTR + (lane >> 4) * 16;
    const uint32_t vlo = (uint32_t)(((lane >> 4) << 3) + (lane & 7)) * ASTR
                         + ((lane >> 3) & 1) * 16;

    float o[16][4];
#pragma unroll
    for (int nb = 0; nb < 16; ++nb)
#pragma unroll
        for (int e = 0; e < 4; ++e) o[nb][e] = 0.f;
    float m_a = -1e30f, m_b = -1e30f, l_a = 0.f, l_b = 0.f;

    const int row_a = qt0 + wm + (lane >> 2);
    const int row_b = row_a + 8;

    const int nkt = (qt0 + 128) / 64;
    for (int kt = 0; kt < nkt; ++kt) {
        if (kt + 1 < nkt) {
            kv_load(kt + 1, (kt + 1) & 1);
            CP_COMMIT();
            CP_WAIT(1);
        } else {
            CP_WAIT(0);
        }
        __syncthreads();

        if (kt * 64 <= qt0 + wm + 15) {
            const uint32_t stb = sb + OFF_KV + (kt & 1) * KVSTAGE;
            const uint32_t kb = stb + klo;
            const uint32_t vb = stb + KVTILE + vlo;

            // ---- scores ----
            float sacc[8][4];
#pragma unroll
            for (int nb = 0; nb < 8; ++nb)
#pragma unroll
                for (int e = 0; e < 4; ++e) sacc[nb][e] = 0.f;

#pragma unroll
            for (int ks = 0; ks < 8; ++ks) {
                uint32_t ah[4], al[4];
                ldsm4(ah, qbh + ks * 32);
                ldsm4(al, qbl + ks * 32);
#pragma unroll
                for (int pg = 0; pg < 4; ++pg) {
                    uint32_t bk[4];
                    ldsm4(bk, kb + pg * 16 * ASTR + ks * 32);
                    mma_f16(sacc[pg * 2],     ah, bk[0], bk[2]);
                    mma_f16(sacc[pg * 2],     al, bk[0], bk[2]);
                    mma_f16(sacc[pg * 2 + 1], ah, bk[1], bk[3]);
                    mma_f16(sacc[pg * 2 + 1], al, bk[1], bk[3]);
                }
            }

            // ---- causal mask ----
            if (kt * 64 + 63 > qt0 + wm) {
#pragma unroll
                for (int nb = 0; nb < 8; ++nb) {
                    const int col = kt * 64 + nb * 8 + (lane & 3) * 2;
                    if (col > row_a)     sacc[nb][0] = -1e30f;
                    if (col + 1 > row_a) sacc[nb][1] = -1e30f;
                    if (col > row_b)     sacc[nb][2] = -1e30f;
                    if (col + 1 > row_b) sacc[nb][3] = -1e30f;
                }
            }

            // ---- online softmax ----
            float mx_a = -1e30f, mx_b = -1e30f;
#pragma unroll
            for (int nb = 0; nb < 8; ++nb) {
                mx_a = fmaxf(mx_a, fmaxf(sacc[nb][0], sacc[nb][1]));
                mx_b = fmaxf(mx_b, fmaxf(sacc[nb][2], sacc[nb][3]));
            }
            mx_a = fmaxf(mx_a, __shfl_xor_sync(0xffffffffu, mx_a, 1));
            mx_a = fmaxf(mx_a, __shfl_xor_sync(0xffffffffu, mx_a, 2));
            mx_b = fmaxf(mx_b, __shfl_xor_sync(0xffffffffu, mx_b, 1));
            mx_b = fmaxf(mx_b, __shfl_xor_sync(0xffffffffu, mx_b, 2));

            const float mn_a = fmaxf(m_a, mx_a);
            const float mn_b = fmaxf(m_b, mx_b);
            const float al_a = __expf(m_a - mn_a);
            const float al_b = __expf(m_b - mn_b);
            m_a = mn_a; m_b = mn_b;

            float sum_a = 0.f, sum_b = 0.f;
#pragma unroll
            for (int nb = 0; nb < 8; ++nb) {
                sacc[nb][0] = __expf(sacc[nb][0] - mn_a);
                sacc[nb][1] = __expf(sacc[nb][1] - mn_a);
                sacc[nb][2] = __expf(sacc[nb][2] - mn_b);
                sacc[nb][3] = __expf(sacc[nb][3] - mn_b);
                sum_a += sacc[nb][0] + sacc[nb][1];
                sum_b += sacc[nb][2] + sacc[nb][3];
            }
            sum_a += __shfl_xor_sync(0xffffffffu, sum_a, 1);
            sum_a += __shfl_xor_sync(0xffffffffu, sum_a, 2);
            sum_b += __shfl_xor_sync(0xffffffffu, sum_b, 1);
            sum_b += __shfl_xor_sync(0xffffffffu, sum_b, 2);
            l_a = l_a * al_a + sum_a;
            l_b = l_b * al_b + sum_b;

#pragma unroll
            for (int nb = 0; nb < 16; ++nb) {
                o[nb][0] *= al_a; o[nb][1] *= al_a;
                o[nb][2] *= al_b; o[nb][3] *= al_b;
            }

            // ---- PV: P single fp16, V single fp16 ----
#pragma unroll
            for (int kc = 0; kc < 4; ++kc) {
                uint32_t p[4];
                p[0] = packh2(sacc[2 * kc][0],     sacc[2 * kc][1]);
                p[1] = packh2(sacc[2 * kc][2],     sacc[2 * kc][3]);
                p[2] = packh2(sacc[2 * kc + 1][0], sacc[2 * kc + 1][1]);
                p[3] = packh2(sacc[2 * kc + 1][2], sacc[2 * kc + 1][3]);
#pragma unroll
                for (int pg = 0; pg < 8; ++pg) {
                    uint32_t vv[4];
                    ldsm4t(vv, vb + kc * 16 * ASTR + pg * 32);
                    mma_f16(o[pg * 2],     p, vv[0], vv[2]);
                    mma_f16(o[pg * 2 + 1], p, vv[1], vv[3]);
                }
            }
        }
        __syncthreads();
    }

    // ---- epilogue: single fp16 output ----
    const float inv_a = 1.f / l_a;
    const float inv_b = 1.f / l_b;
    const size_t oa = (size_t)(b * S_LEN + row_a) * D_OUT + h * DH;
    const size_t ob = (size_t)(b * S_LEN + row_b) * D_OUT + h * DH;
#pragma unroll
    for (int nb = 0; nb < 16; ++nb) {
        const int col = nb * 8 + (lane & 3) * 2;
        *(uint32_t*)(oh + oa + col) = packh2(o[nb][0] * inv_a, o[nb][1] * inv_a);
        *(uint32_t*)(oh + ob + col) = packh2(o[nb][2] * inv_b, o[nb][3] * inv_b);
    }
}

// ---------------------------------------------------------------------------
// Launch
// ---------------------------------------------------------------------------
extern "C" void kernel_launch(void* const* d_in, const int* in_sizes, int n_in,
                              void* d_out, int out_size)
{
    const float* x      = (const float*)d_in[0];
    const float* w_qkv  = (const float*)d_in[1];
    const float* w_proj = (const float*)d_in[2];
    const float* b_proj = (const float*)d_in[3];
    float* out = (float*)d_out;

    void *x16, *wqh, *wql, *wph, *wpl, *qkvh, *qkvl, *a16;
    cudaGetSymbolAddress(&x16, g_x16);
    cudaGetSymbolAddress(&wqh, g_wqh); cudaGetSymbolAddress(&wql, g_wql);
    cudaGetSymbolAddress(&wph, g_wph); cudaGetSymbolAddress(&wpl, g_wpl);
    cudaGetSymbolAddress(&qkvh, g_qkvh); cudaGetSymbolAddress(&qkvl, g_qkvl);
    cudaGetSymbolAddress(&a16, g_a16);

    cudaFuncSetAttribute(mma_gemm, cudaFuncAttributeMaxDynamicSharedMemorySize, GEMM_SMEM);
    cudaFuncSetAttribute(attn_mma, cudaFuncAttributeMaxDynamicSharedMemorySize, ATTN_SMEM_B);

    // 0) conversions
    {
        int n4;
        n4 = M_TOK * D_IN / 4;
        tohalf_k<<<(n4 + 255) / 256, 256>>>((const float4*)x, (uint2*)x16, n4);
        n4 = D3 * D_IN / 4;
        splith_k<<<(n4 + 255) / 256, 256>>>((const float4*)w_qkv, (uint2*)wqh, (uint2*)wql, n4);
        n4 = D_OUT * D_OUT / 4;
        splith_k<<<(n4 + 255) / 256, 256>>>((const float4*)w_proj, (uint2*)wph, (uint2*)wpl, n4);
    }

    // 1) QKV projection -> split fp16 qkv (Q cols pre-scaled)
    mma_gemm<<<dim3(D3 / 128, M_TOK / 128), 256, GEMM_SMEM>>>(
        (const __half*)x16, (const __half*)wqh, (const __half*)wql,
        nullptr, nullptr, (__half*)qkvh, (__half*)qkvl,
        M_TOK, D3, D_IN, QSCALE, D_OUT);

    // 2) Fused causal attention -> single fp16
    attn_mma<<<dim3(S_LEN / 128, B_SZ * NHEAD), 256, ATTN_SMEM_B>>>(
        (const __half*)qkvh, (const __half*)qkvl, (__half*)a16);

    // 3) Output projection + bias -> f32 out
    mma_gemm<<<dim3(D_OUT / 128, M_TOK / 128), 256, GEMM_SMEM>>>(
        (const __half*)a16, (const __half*)wph, (const __half*)wpl,
        b_proj, out, nullptr, nullptr,
        M_TOK, D_OUT, D_OUT, 1.f, 0);
}